// round 13
// baseline (speedup 1.0000x reference)
#include <cuda_runtime.h>
#include <cuda_fp16.h>
#include <math.h>

#define NN   1024
#define HH   128
#define DD   256
#define NLVL 3
#define LN_EPS 1e-5f

// -------- device scratch (static: allocation-free kernel_launch) --------
__device__ float g_x[NN*HH];
__device__ float g_pre[NN*HH];
__device__ float g_prj[NN*HH];
__device__ float g_msum[NN*HH];
__device__ float g_esum[NN*HH];     // sum_j ew[i,j,h]  (level-invariant)
__device__ float g_lmean[NLVL*HH];
// UPPER TRIANGLE ONLY (j >= i) is populated; ew symmetric in (i,j).
// ~134 MB touched -> mostly L2-resident across the 3 msum passes.
__device__ __half g_ew[(long long)NN*NN*HH];

// 1-MUFU silu: silu(x) = 0.5*x*(1 + tanh(0.5*x))
__device__ __forceinline__ float silu_f(float x) {
    float t;
    asm("tanh.approx.f32 %0, %1;" : "=f"(t) : "f"(x * 0.5f));
    float hx = 0.5f * x;
    return fmaf(hx, t, hx);
}

__device__ __forceinline__ float warp_sum(float v) {
    #pragma unroll
    for (int off = 16; off; off >>= 1)
        v += __shfl_xor_sync(0xffffffffu, v, off);
    return v;
}

// ---------------------------------------------------------------
__global__ void k_init(const int* __restrict__ an, const float* __restrict__ emb) {
    int t = blockIdx.x * blockDim.x + threadIdx.x;
    if (t < NLVL*HH) g_lmean[t] = 0.f;
    int n = t >> 7;
    int h = t & 127;
    g_x[t] = emb[an[n]*HH + h];
}

// ---------------------------------------------------------------
// ew[i,j,:] (j>=i only) = LN(silu(scales @ de_W + de_b))*de_g + de_be (fp16)
// Persistent: 512 blocks; block b covers rows {b, 1023-b} (constant work).
// 16 lanes per pair (8 h each), 2 pairs per warp. NO mirror store.
__global__ void __launch_bounds__(256) k_ew(
    const float* __restrict__ pos,
    const float* __restrict__ deW, const float* __restrict__ deb,
    const float* __restrict__ deg, const float* __restrict__ debe)
{
    int warp = threadIdx.x >> 5;
    int lane = threadIdx.x & 31;
    int grp  = lane >> 4;
    int l16  = lane & 15;
    int h0   = l16 << 3;
    int jfix = (warp << 1) + grp;        // 0..15

    float w0[8], w1[8], w2[8], wb[8], wg[8], we[8];
    *(float4*)(w0)   = *(const float4*)(deW + h0);
    *(float4*)(w0+4) = *(const float4*)(deW + h0 + 4);
    *(float4*)(w1)   = *(const float4*)(deW + HH + h0);
    *(float4*)(w1+4) = *(const float4*)(deW + HH + h0 + 4);
    *(float4*)(w2)   = *(const float4*)(deW + 2*HH + h0);
    *(float4*)(w2+4) = *(const float4*)(deW + 2*HH + h0 + 4);
    *(float4*)(wb)   = *(const float4*)(deb + h0);
    *(float4*)(wb+4) = *(const float4*)(deb + h0 + 4);
    *(float4*)(wg)   = *(const float4*)(deg + h0);
    *(float4*)(wg+4) = *(const float4*)(deg + h0 + 4);
    *(float4*)(we)   = *(const float4*)(debe + h0);
    *(float4*)(we+4) = *(const float4*)(debe + h0 + 4);

    #pragma unroll
    for (int half = 0; half < 2; half++) {
        int i = half ? (NN - 1 - (int)blockIdx.x) : (int)blockIdx.x;
        float pix = pos[3*i], piy = pos[3*i+1], piz = pos[3*i+2];

        int nt = (NN - i + 15) >> 4;
        for (int it = 0; it < nt; it++) {
            int j   = i + jfix + (it << 4);
            bool ok = (j < NN);
            int jc  = ok ? j : (NN - 1);

            float dx = pix - pos[3*jc];
            float dy = piy - pos[3*jc+1];
            float dz = piz - pos[3*jc+2];
            float sq = dx*dx + dy*dy + dz*dz;
            float d  = (sq > 0.f) ? sqrtf(sq) : 0.f;
            float s3 = __expf(-0.25f * d);
            float s2 = s3 * s3;
            float s1 = s2 * s2;

            float v[8];
            #pragma unroll
            for (int k = 0; k < 8; k++)
                v[k] = silu_f(fmaf(s1, w0[k], fmaf(s2, w1[k], fmaf(s3, w2[k], wb[k]))));

            float p = ((v[0]+v[1])+(v[2]+v[3])) + ((v[4]+v[5])+(v[6]+v[7]));
            float q = fmaf(v[0],v[0], fmaf(v[1],v[1], fmaf(v[2],v[2], v[3]*v[3])))
                    + fmaf(v[4],v[4], fmaf(v[5],v[5], fmaf(v[6],v[6], v[7]*v[7])));
            #pragma unroll
            for (int off = 8; off; off >>= 1) {
                p += __shfl_xor_sync(0xffffffffu, p, off);
                q += __shfl_xor_sync(0xffffffffu, q, off);
            }
            float mu   = p * (1.f/HH);
            float var  = fmaf(-mu, mu, q * (1.f/HH));
            float rstd = rsqrtf(var + LN_EPS);
            float c0   = -mu * rstd;

            __half2 oh[4];
            #pragma unroll
            for (int k = 0; k < 4; k++) {
                float oa = fmaf(fmaf(v[2*k],   rstd, c0), wg[2*k],   we[2*k]);
                float ob = fmaf(fmaf(v[2*k+1], rstd, c0), wg[2*k+1], we[2*k+1]);
                oh[k] = __floats2half2_rn(oa, ob);
            }
            uint4 pack;
            pack.x = *(unsigned*)&oh[0]; pack.y = *(unsigned*)&oh[1];
            pack.z = *(unsigned*)&oh[2]; pack.w = *(unsigned*)&oh[3];

            if (ok)   // plain store: keep in L2 for the msum passes
                *(uint4*)(g_ew + ((long long)i*NN + j)*HH + h0) = pack;
        }
    }
}

// ---------------------------------------------------------------
// pre = x@Wi + msg_b, prj = x@Wj.  8 nodes/block, 128 threads (h).
__global__ void __launch_bounds__(128) k_preprj(
    const float* __restrict__ msgW, const float* __restrict__ msgb, int lvl)
{
    __shared__ float xs[8][HH];
    int h  = threadIdx.x;
    int n0 = blockIdx.x << 3;
    #pragma unroll
    for (int nn = 0; nn < 8; nn++) xs[nn][h] = g_x[(n0+nn)*HH + h];
    __syncthreads();

    const float* Wi = msgW + (size_t)lvl*2*HH*HH;
    const float* Wj = Wi + HH*HH;
    float ai[8], aj[8];
    #pragma unroll
    for (int nn = 0; nn < 8; nn++) { ai[nn] = 0.f; aj[nn] = 0.f; }

    for (int k = 0; k < HH; k++) {
        float wi = Wi[k*HH + h];
        float wj = Wj[k*HH + h];
        #pragma unroll
        for (int nn = 0; nn < 8; nn++) {
            ai[nn] = fmaf(xs[nn][k], wi, ai[nn]);
            aj[nn] = fmaf(xs[nn][k], wj, aj[nn]);
        }
    }
    float bb = msgb[lvl*HH + h];
    #pragma unroll
    for (int nn = 0; nn < 8; nn++) {
        g_pre[(n0+nn)*HH + h] = ai[nn] + bb;
        g_prj[(n0+nn)*HH + h] = aj[nn];
    }
}

// ---------------------------------------------------------------
// msum[i,h] = g[h]*sum_j (s-mu)*rstd*e  +  be[h]*sum_j e
// Two-phase j loop over the symmetric triangle storage:
//   phase 1: j in [0,i)  -> ew[j*NN + i]   (column home)
//   phase 2: j in [i,NN) -> ew[i*NN + j]   (row home)
// 16 lanes per j (8 h each), 2 j per warp; tails predicated.
template<bool FIRST>
__global__ void __launch_bounds__(256) k_msum(
    const float* __restrict__ msgg, const float* __restrict__ msgbe, int lvl)
{
    __shared__ float red[16][HH];
    __shared__ float red2[16][HH];
    int i    = blockIdx.x;
    int warp = threadIdx.x >> 5;
    int lane = threadIdx.x & 31;
    int grp  = lane >> 4;
    int l16  = lane & 15;
    int h0   = l16 << 3;

    float pre[8];
    *(float4*)(pre)     = *(const float4*)(g_pre + i*HH + h0);
    *(float4*)(pre + 4) = *(const float4*)(g_pre + i*HH + h0 + 4);

    float a[8] = {0,0,0,0,0,0,0,0};
    float z[8] = {0,0,0,0,0,0,0,0};
    int jfix = (warp << 1) + grp;

    // ---- phase 1: j < i, ew home = (j, i) ----
    {
        int nt = (i + 15) >> 4;
        for (int it = 0; it < nt; it++) {
            int j   = (it << 4) + jfix;          // j <= 1023 always
            bool ok = (j < i);
            float4 pja = *(const float4*)(g_prj + j*HH + h0);
            float4 pjb = *(const float4*)(g_prj + j*HH + h0 + 4);
            uint4  epk = *(const uint4*)(g_ew + ((long long)j*NN + i)*HH + h0);

            float s[8];
            s[0] = silu_f(pre[0] + pja.x);
            s[1] = silu_f(pre[1] + pja.y);
            s[2] = silu_f(pre[2] + pja.z);
            s[3] = silu_f(pre[3] + pja.w);
            s[4] = silu_f(pre[4] + pjb.x);
            s[5] = silu_f(pre[5] + pjb.y);
            s[6] = silu_f(pre[6] + pjb.z);
            s[7] = silu_f(pre[7] + pjb.w);

            float p = ((s[0]+s[1])+(s[2]+s[3])) + ((s[4]+s[5])+(s[6]+s[7]));
            float q = fmaf(s[0],s[0], fmaf(s[1],s[1], fmaf(s[2],s[2], s[3]*s[3])))
                    + fmaf(s[4],s[4], fmaf(s[5],s[5], fmaf(s[6],s[6], s[7]*s[7])));
            #pragma unroll
            for (int off = 8; off; off >>= 1) {
                p += __shfl_xor_sync(0xffffffffu, p, off);
                q += __shfl_xor_sync(0xffffffffu, q, off);
            }
            float mu   = p * (1.f/HH);
            float var  = fmaf(-mu, mu, q * (1.f/HH));
            float rstd = rsqrtf(var + LN_EPS);
            float c0   = -mu * rstd;

            unsigned u0 = epk.x, u1 = epk.y, u2 = epk.z, u3 = epk.w;
            float2 f0 = __half22float2(*(__half2*)&u0);
            float2 f1 = __half22float2(*(__half2*)&u1);
            float2 f2 = __half22float2(*(__half2*)&u2);
            float2 f3 = __half22float2(*(__half2*)&u3);
            float e[8] = { f0.x, f0.y, f1.x, f1.y, f2.x, f2.y, f3.x, f3.y };

            if (ok) {
                #pragma unroll
                for (int k = 0; k < 8; k++) {
                    a[k] = fmaf(fmaf(s[k], rstd, c0), e[k], a[k]);
                    if (FIRST) z[k] += e[k];
                }
            }
        }
    }

    // ---- phase 2: j >= i, ew home = (i, j) ----
    {
        int nt = (NN - i + 15) >> 4;
        const __half* ewrow = g_ew + (long long)i*NN*HH + h0;
        for (int it = 0; it < nt; it++) {
            int j   = i + (it << 4) + jfix;
            bool ok = (j < NN);
            int jc  = ok ? j : (NN - 1);
            float4 pja = *(const float4*)(g_prj + jc*HH + h0);
            float4 pjb = *(const float4*)(g_prj + jc*HH + h0 + 4);
            uint4  epk = *(const uint4*)(ewrow + (long long)jc*HH);

            float s[8];
            s[0] = silu_f(pre[0] + pja.x);
            s[1] = silu_f(pre[1] + pja.y);
            s[2] = silu_f(pre[2] + pja.z);
            s[3] = silu_f(pre[3] + pja.w);
            s[4] = silu_f(pre[4] + pjb.x);
            s[5] = silu_f(pre[5] + pjb.y);
            s[6] = silu_f(pre[6] + pjb.z);
            s[7] = silu_f(pre[7] + pjb.w);

            float p = ((s[0]+s[1])+(s[2]+s[3])) + ((s[4]+s[5])+(s[6]+s[7]));
            float q = fmaf(s[0],s[0], fmaf(s[1],s[1], fmaf(s[2],s[2], s[3]*s[3])))
                    + fmaf(s[4],s[4], fmaf(s[5],s[5], fmaf(s[6],s[6], s[7]*s[7])));
            #pragma unroll
            for (int off = 8; off; off >>= 1) {
                p += __shfl_xor_sync(0xffffffffu, p, off);
                q += __shfl_xor_sync(0xffffffffu, q, off);
            }
            float mu   = p * (1.f/HH);
            float var  = fmaf(-mu, mu, q * (1.f/HH));
            float rstd = rsqrtf(var + LN_EPS);
            float c0   = -mu * rstd;

            unsigned u0 = epk.x, u1 = epk.y, u2 = epk.z, u3 = epk.w;
            float2 f0 = __half22float2(*(__half2*)&u0);
            float2 f1 = __half22float2(*(__half2*)&u1);
            float2 f2 = __half22float2(*(__half2*)&u2);
            float2 f3 = __half22float2(*(__half2*)&u3);
            float e[8] = { f0.x, f0.y, f1.x, f1.y, f2.x, f2.y, f3.x, f3.y };

            if (ok) {
                #pragma unroll
                for (int k = 0; k < 8; k++) {
                    a[k] = fmaf(fmaf(s[k], rstd, c0), e[k], a[k]);
                    if (FIRST) z[k] += e[k];
                }
            }
        }
    }

    int slot = (warp << 1) | grp;
    #pragma unroll
    for (int k = 0; k < 8; k++) red[slot][h0+k] = a[k];
    if (FIRST) {
        #pragma unroll
        for (int k = 0; k < 8; k++) red2[slot][h0+k] = z[k];
    }
    __syncthreads();
    if (threadIdx.x < HH) {
        int h = threadIdx.x;
        float S1 = 0.f, S0 = 0.f;
        #pragma unroll
        for (int w = 0; w < 16; w++) S1 += red[w][h];
        if (FIRST) {
            #pragma unroll
            for (int w = 0; w < 16; w++) S0 += red2[w][h];
            g_esum[i*HH + h] = S0;
        } else {
            S0 = g_esum[i*HH + h];
        }
        g_msum[i*HH + h] = fmaf(msgg[lvl*HH + h], S1, msgbe[lvl*HH + h] * S0);
    }
}

// ---------------------------------------------------------------
// x += LN(silu([x, msum] @ upd_W + upd_b)); accumulate level mean.
__global__ void __launch_bounds__(128) k_upd(
    const float* __restrict__ updW, const float* __restrict__ updb,
    const float* __restrict__ updg, const float* __restrict__ updbe, int lvl)
{
    __shared__ float us[2*HH];
    __shared__ float rp[4], rq[4];
    __shared__ float s_mu, s_rstd;
    int i = blockIdx.x;
    int h = threadIdx.x;
    int warp = h >> 5, lane = h & 31;

    us[h]      = g_x[i*HH + h];
    us[HH + h] = g_msum[i*HH + h];
    __syncthreads();

    const float* W = updW + (size_t)lvl*2*HH*HH;
    float acc = updb[lvl*HH + h];
    #pragma unroll 4
    for (int k = 0; k < 2*HH; k++) acc = fmaf(us[k], W[k*HH + h], acc);

    float s = silu_f(acc);

    float p = warp_sum(s);
    float q = warp_sum(s*s);
    if (lane == 0) { rp[warp] = p; rq[warp] = q; }
    __syncthreads();
    if (h == 0) {
        float P = rp[0]+rp[1]+rp[2]+rp[3];
        float Q = rq[0]+rq[1]+rq[2]+rq[3];
        float mu = P * (1.f/HH);
        s_mu = mu;
        s_rstd = rsqrtf(fmaf(-mu, mu, Q * (1.f/HH)) + LN_EPS);
    }
    __syncthreads();

    float m  = fmaf((s - s_mu) * s_rstd, updg[lvl*HH + h], updbe[lvl*HH + h]);
    float xn = us[h] + m;
    g_x[i*HH + h] = xn;
    atomicAdd(&g_lmean[lvl*HH + h], xn * (1.f/NN));
}

// ---------------------------------------------------------------
__global__ void __launch_bounds__(256) k_final(
    const float* __restrict__ fpW, const float* __restrict__ fpb,
    const float* __restrict__ fpg, const float* __restrict__ fpbe,
    float* __restrict__ out)
{
    __shared__ float cs[NLVL*HH];
    __shared__ float rp[8], rq[8];
    __shared__ float s_mu, s_rstd;
    int t = threadIdx.x;
    int warp = t >> 5, lane = t & 31;

    for (int k = t; k < NLVL*HH; k += 256) cs[k] = g_lmean[k];
    __syncthreads();

    float acc = fpb[t];
    #pragma unroll 4
    for (int k = 0; k < NLVL*HH; k++) acc = fmaf(cs[k], fpW[k*DD + t], acc);

    float p = warp_sum(acc);
    float q = warp_sum(acc*acc);
    if (lane == 0) { rp[warp] = p; rq[warp] = q; }
    __syncthreads();
    if (t == 0) {
        float P = 0.f, Q = 0.f;
        #pragma unroll
        for (int w = 0; w < 8; w++) { P += rp[w]; Q += rq[w]; }
        float mu = P * (1.f/DD);
        s_mu = mu;
        s_rstd = rsqrtf(fmaf(-mu, mu, Q * (1.f/DD)) + LN_EPS);
    }
    __syncthreads();

    out[t] = fmaf((acc - s_mu) * s_rstd, fpg[t], fpbe[t]);
}

// ---------------------------------------------------------------
extern "C" void kernel_launch(void* const* d_in, const int* in_sizes, int n_in,
                              void* d_out, int out_size) {
    const int*   an    = (const int*)  d_in[0];
    const float* pos   = (const float*)d_in[1];
    const float* emb   = (const float*)d_in[2];
    const float* deW   = (const float*)d_in[3];
    const float* deb   = (const float*)d_in[4];
    const float* deg   = (const float*)d_in[5];
    const float* debe  = (const float*)d_in[6];
    const float* msgW  = (const float*)d_in[7];
    const float* msgb  = (const float*)d_in[8];
    const float* msgg  = (const float*)d_in[9];
    const float* msgbe = (const float*)d_in[10];
    const float* updW  = (const float*)d_in[11];
    const float* updb  = (const float*)d_in[12];
    const float* updg  = (const float*)d_in[13];
    const float* updbe = (const float*)d_in[14];
    const float* fpW   = (const float*)d_in[15];
    const float* fpb   = (const float*)d_in[16];
    const float* fpg   = (const float*)d_in[17];
    const float* fpbe  = (const float*)d_in[18];
    float* out = (float*)d_out;

    k_init<<<512, 256>>>(an, emb);
    k_ew<<<512, 256>>>(pos, deW, deb, deg, debe);
    for (int lvl = 0; lvl < NLVL; lvl++) {
        k_preprj<<<128, 128>>>(msgW, msgb, lvl);
        if (lvl == 0) k_msum<true><<<1024, 256>>>(msgg, msgbe, lvl);
        else          k_msum<false><<<1024, 256>>>(msgg, msgbe, lvl);
        k_upd<<<1024, 128>>>(updW, updb, updg, updbe, lvl);
    }
    k_final<<<1, 256>>>(fpW, fpb, fpg, fpbe, out);
}

// round 14
// speedup vs baseline: 1.3628x; 1.3628x over previous
#include <cuda_runtime.h>
#include <cuda_fp16.h>
#include <math.h>

#define NN   1024
#define HH   128
#define DD   256
#define NLVL 3
#define LN_EPS 1e-5f

// -------- device scratch (static: allocation-free kernel_launch) --------
__device__ float g_x[NN*HH];
__device__ float g_pre[NN*HH];
__device__ float g_prj[NN*HH];
__device__ float g_msum[NN*HH];
__device__ float g_esum[NN*HH];     // sum_j ew[i,j,h]  (level-invariant)
__device__ float g_lmean[NLVL*HH];
__device__ __half g_ew[(long long)NN*NN*HH];  // full matrix, written by k_msum0

// 1-MUFU silu: silu(x) = 0.5*x*(1 + tanh(0.5*x))
__device__ __forceinline__ float silu_f(float x) {
    float t;
    asm("tanh.approx.f32 %0, %1;" : "=f"(t) : "f"(x * 0.5f));
    float hx = 0.5f * x;
    return fmaf(hx, t, hx);
}

__device__ __forceinline__ float warp_sum(float v) {
    #pragma unroll
    for (int off = 16; off; off >>= 1)
        v += __shfl_xor_sync(0xffffffffu, v, off);
    return v;
}

// ---------------------------------------------------------------
__global__ void k_init(const int* __restrict__ an, const float* __restrict__ emb) {
    int t = blockIdx.x * blockDim.x + threadIdx.x;
    if (t < NLVL*HH) g_lmean[t] = 0.f;
    int n = t >> 7;
    int h = t & 127;
    g_x[t] = emb[an[n]*HH + h];
}

// ---------------------------------------------------------------
// pre = x@Wi + msg_b, prj = x@Wj.  8 nodes/block, 128 threads (h).
__global__ void __launch_bounds__(128) k_preprj(
    const float* __restrict__ msgW, const float* __restrict__ msgb, int lvl)
{
    __shared__ float xs[8][HH];
    int h  = threadIdx.x;
    int n0 = blockIdx.x << 3;
    #pragma unroll
    for (int nn = 0; nn < 8; nn++) xs[nn][h] = g_x[(n0+nn)*HH + h];
    __syncthreads();

    const float* Wi = msgW + (size_t)lvl*2*HH*HH;
    const float* Wj = Wi + HH*HH;
    float ai[8], aj[8];
    #pragma unroll
    for (int nn = 0; nn < 8; nn++) { ai[nn] = 0.f; aj[nn] = 0.f; }

    for (int k = 0; k < HH; k++) {
        float wi = Wi[k*HH + h];
        float wj = Wj[k*HH + h];
        #pragma unroll
        for (int nn = 0; nn < 8; nn++) {
            ai[nn] = fmaf(xs[nn][k], wi, ai[nn]);
            aj[nn] = fmaf(xs[nn][k], wj, aj[nn]);
        }
    }
    float bb = msgb[lvl*HH + h];
    #pragma unroll
    for (int nn = 0; nn < 8; nn++) {
        g_pre[(n0+nn)*HH + h] = ai[nn] + bb;
        g_prj[(n0+nn)*HH + h] = aj[nn];
    }
}

// ---------------------------------------------------------------
// LEVEL 0, fused: computes ew[i,j,:] inline (distances + de-GEMM + LN),
// uses it for msum, and stores fp16 full row for levels 1-2.
// Accumulates P1=sum s~*v~, P2=sum s~, P3=sum v~ per h; wg/we/msgg/msgbe
// folded in the epilogue.  16 lanes per j, 8 h/lane, 2 j/warp.
__global__ void __launch_bounds__(256) k_msum0(
    const float* __restrict__ pos,
    const float* __restrict__ deW, const float* __restrict__ deb,
    const float* __restrict__ deg, const float* __restrict__ debe,
    const float* __restrict__ msgg, const float* __restrict__ msgbe)
{
    __shared__ float red1[16][HH];
    __shared__ float red2[16][HH];
    __shared__ float red3[16][HH];
    int i    = blockIdx.x;
    int warp = threadIdx.x >> 5;
    int lane = threadIdx.x & 31;
    int grp  = lane >> 4;
    int l16  = lane & 15;
    int h0   = l16 << 3;
    int jfix = (warp << 1) + grp;

    float pre[8];
    *(float4*)(pre)     = *(const float4*)(g_pre + i*HH + h0);
    *(float4*)(pre + 4) = *(const float4*)(g_pre + i*HH + h0 + 4);

    // de weights in registers (per-h0 slice)
    float w0[8], w1[8], w2[8], wb[8], wg[8], we[8];
    *(float4*)(w0)   = *(const float4*)(deW + h0);
    *(float4*)(w0+4) = *(const float4*)(deW + h0 + 4);
    *(float4*)(w1)   = *(const float4*)(deW + HH + h0);
    *(float4*)(w1+4) = *(const float4*)(deW + HH + h0 + 4);
    *(float4*)(w2)   = *(const float4*)(deW + 2*HH + h0);
    *(float4*)(w2+4) = *(const float4*)(deW + 2*HH + h0 + 4);
    *(float4*)(wb)   = *(const float4*)(deb + h0);
    *(float4*)(wb+4) = *(const float4*)(deb + h0 + 4);
    *(float4*)(wg)   = *(const float4*)(deg + h0);
    *(float4*)(wg+4) = *(const float4*)(deg + h0 + 4);
    *(float4*)(we)   = *(const float4*)(debe + h0);
    *(float4*)(we+4) = *(const float4*)(debe + h0 + 4);

    float pix = pos[3*i], piy = pos[3*i+1], piz = pos[3*i+2];

    float P1[8] = {0,0,0,0,0,0,0,0};
    float P2[8] = {0,0,0,0,0,0,0,0};
    float P3[8] = {0,0,0,0,0,0,0,0};

    __half* ewrow = g_ew + (long long)i*NN*HH + h0;

    #pragma unroll 2
    for (int jj = 0; jj < NN/16; jj++) {
        int j = (jj << 4) + jfix;
        float4 pja = *(const float4*)(g_prj + j*HH + h0);
        float4 pjb = *(const float4*)(g_prj + j*HH + h0 + 4);

        // --- ew scalars ---
        float dx = pix - pos[3*j];
        float dy = piy - pos[3*j+1];
        float dz = piz - pos[3*j+2];
        float sq = dx*dx + dy*dy + dz*dz;
        float d  = (sq > 0.f) ? sqrtf(sq) : 0.f;
        float s3 = __expf(-0.25f * d);
        float s2 = s3 * s3;
        float s1 = s2 * s2;

        float v[8];
        #pragma unroll
        for (int k = 0; k < 8; k++)
            v[k] = silu_f(fmaf(s1, w0[k], fmaf(s2, w1[k], fmaf(s3, w2[k], wb[k]))));

        float s[8];
        s[0] = silu_f(pre[0] + pja.x);
        s[1] = silu_f(pre[1] + pja.y);
        s[2] = silu_f(pre[2] + pja.z);
        s[3] = silu_f(pre[3] + pja.w);
        s[4] = silu_f(pre[4] + pjb.x);
        s[5] = silu_f(pre[5] + pjb.y);
        s[6] = silu_f(pre[6] + pjb.z);
        s[7] = silu_f(pre[7] + pjb.w);

        // interleaved 4-chain butterflies (16-lane groups)
        float pv = ((v[0]+v[1])+(v[2]+v[3])) + ((v[4]+v[5])+(v[6]+v[7]));
        float qv = fmaf(v[0],v[0], fmaf(v[1],v[1], fmaf(v[2],v[2], v[3]*v[3])))
                 + fmaf(v[4],v[4], fmaf(v[5],v[5], fmaf(v[6],v[6], v[7]*v[7])));
        float ps = ((s[0]+s[1])+(s[2]+s[3])) + ((s[4]+s[5])+(s[6]+s[7]));
        float qs = fmaf(s[0],s[0], fmaf(s[1],s[1], fmaf(s[2],s[2], s[3]*s[3])))
                 + fmaf(s[4],s[4], fmaf(s[5],s[5], fmaf(s[6],s[6], s[7]*s[7])));
        #pragma unroll
        for (int off = 8; off; off >>= 1) {
            pv += __shfl_xor_sync(0xffffffffu, pv, off);
            qv += __shfl_xor_sync(0xffffffffu, qv, off);
            ps += __shfl_xor_sync(0xffffffffu, ps, off);
            qs += __shfl_xor_sync(0xffffffffu, qs, off);
        }
        float muv   = pv * (1.f/HH);
        float rstdv = rsqrtf(fmaf(-muv, muv, qv * (1.f/HH)) + LN_EPS);
        float c0v   = -muv * rstdv;
        float mus   = ps * (1.f/HH);
        float rstds = rsqrtf(fmaf(-mus, mus, qs * (1.f/HH)) + LN_EPS);
        float c0s   = -mus * rstds;

        float vt[8], e[8];
        #pragma unroll
        for (int k = 0; k < 8; k++) {
            vt[k]    = fmaf(v[k], rstdv, c0v);
            float st = fmaf(s[k], rstds, c0s);
            P1[k] = fmaf(st, vt[k], P1[k]);
            P2[k] += st;
            P3[k] += vt[k];
            e[k] = fmaf(vt[k], wg[k], we[k]);
        }
        __half2 oh[4];
        #pragma unroll
        for (int k = 0; k < 4; k++)
            oh[k] = __floats2half2_rn(e[2*k], e[2*k+1]);
        uint4 pack;
        pack.x = *(unsigned*)&oh[0]; pack.y = *(unsigned*)&oh[1];
        pack.z = *(unsigned*)&oh[2]; pack.w = *(unsigned*)&oh[3];
        __stcs((uint4*)(ewrow + (long long)j*HH), pack);
    }

    int slot = (warp << 1) | grp;
    #pragma unroll
    for (int k = 0; k < 8; k++) {
        red1[slot][h0+k] = P1[k];
        red2[slot][h0+k] = P2[k];
        red3[slot][h0+k] = P3[k];
    }
    __syncthreads();
    if (threadIdx.x < HH) {
        int h = threadIdx.x;
        float S1 = 0.f, S2 = 0.f, S3 = 0.f;
        #pragma unroll
        for (int w = 0; w < 16; w++) { S1 += red1[w][h]; S2 += red2[w][h]; S3 += red3[w][h]; }
        float wgh = deg[h], weh = debe[h];
        float sum_se = fmaf(wgh, S1, weh * S2);   // sum_j s~ * e
        float sum_e  = fmaf(wgh, S3, weh * NN);   // sum_j e
        g_esum[i*HH + h] = sum_e;
        g_msum[i*HH + h] = fmaf(msgg[h], sum_se, msgbe[h] * sum_e);
    }
}

// ---------------------------------------------------------------
// Levels 1-2: R12-proven path — contiguous full-row ew reads, esum reused.
__global__ void __launch_bounds__(256) k_msumN(
    const float* __restrict__ msgg, const float* __restrict__ msgbe, int lvl)
{
    __shared__ float red[16][HH];
    int i    = blockIdx.x;
    int warp = threadIdx.x >> 5;
    int lane = threadIdx.x & 31;
    int grp  = lane >> 4;
    int l16  = lane & 15;
    int h0   = l16 << 3;

    float pre[8];
    *(float4*)(pre)     = *(const float4*)(g_pre + i*HH + h0);
    *(float4*)(pre + 4) = *(const float4*)(g_pre + i*HH + h0 + 4);

    float a[8] = {0,0,0,0,0,0,0,0};
    const __half* ewbase = g_ew + (long long)i*NN*HH + h0;
    int jfix = (warp << 1) + grp;

    #pragma unroll 2
    for (int jj = 0; jj < NN/16; jj++) {
        int j = (jj << 4) + jfix;
        float4 pja = *(const float4*)(g_prj + j*HH + h0);
        float4 pjb = *(const float4*)(g_prj + j*HH + h0 + 4);
        uint4  epk = __ldcs((const uint4*)(ewbase + (long long)j*HH));

        float s[8];
        s[0] = silu_f(pre[0] + pja.x);
        s[1] = silu_f(pre[1] + pja.y);
        s[2] = silu_f(pre[2] + pja.z);
        s[3] = silu_f(pre[3] + pja.w);
        s[4] = silu_f(pre[4] + pjb.x);
        s[5] = silu_f(pre[5] + pjb.y);
        s[6] = silu_f(pre[6] + pjb.z);
        s[7] = silu_f(pre[7] + pjb.w);

        float p = ((s[0]+s[1])+(s[2]+s[3])) + ((s[4]+s[5])+(s[6]+s[7]));
        float q = fmaf(s[0],s[0], fmaf(s[1],s[1], fmaf(s[2],s[2], s[3]*s[3])))
                + fmaf(s[4],s[4], fmaf(s[5],s[5], fmaf(s[6],s[6], s[7]*s[7])));
        #pragma unroll
        for (int off = 8; off; off >>= 1) {
            p += __shfl_xor_sync(0xffffffffu, p, off);
            q += __shfl_xor_sync(0xffffffffu, q, off);
        }
        float mu   = p * (1.f/HH);
        float var  = fmaf(-mu, mu, q * (1.f/HH));
        float rstd = rsqrtf(var + LN_EPS);
        float c0   = -mu * rstd;

        unsigned u0 = epk.x, u1 = epk.y, u2 = epk.z, u3 = epk.w;
        float2 f0 = __half22float2(*(__half2*)&u0);
        float2 f1 = __half22float2(*(__half2*)&u1);
        float2 f2 = __half22float2(*(__half2*)&u2);
        float2 f3 = __half22float2(*(__half2*)&u3);
        float e[8] = { f0.x, f0.y, f1.x, f1.y, f2.x, f2.y, f3.x, f3.y };

        #pragma unroll
        for (int k = 0; k < 8; k++)
            a[k] = fmaf(fmaf(s[k], rstd, c0), e[k], a[k]);
    }

    int slot = (warp << 1) | grp;
    #pragma unroll
    for (int k = 0; k < 8; k++) red[slot][h0+k] = a[k];
    __syncthreads();
    if (threadIdx.x < HH) {
        int h = threadIdx.x;
        float S1 = 0.f;
        #pragma unroll
        for (int w = 0; w < 16; w++) S1 += red[w][h];
        float S0 = g_esum[i*HH + h];
        g_msum[i*HH + h] = fmaf(msgg[lvl*HH + h], S1, msgbe[lvl*HH + h] * S0);
    }
}

// ---------------------------------------------------------------
// x += LN(silu([x, msum] @ upd_W + upd_b)); accumulate level mean.
__global__ void __launch_bounds__(128) k_upd(
    const float* __restrict__ updW, const float* __restrict__ updb,
    const float* __restrict__ updg, const float* __restrict__ updbe, int lvl)
{
    __shared__ float us[2*HH];
    __shared__ float rp[4], rq[4];
    __shared__ float s_mu, s_rstd;
    int i = blockIdx.x;
    int h = threadIdx.x;
    int warp = h >> 5, lane = h & 31;

    us[h]      = g_x[i*HH + h];
    us[HH + h] = g_msum[i*HH + h];
    __syncthreads();

    const float* W = updW + (size_t)lvl*2*HH*HH;
    float acc = updb[lvl*HH + h];
    #pragma unroll 4
    for (int k = 0; k < 2*HH; k++) acc = fmaf(us[k], W[k*HH + h], acc);

    float s = silu_f(acc);

    float p = warp_sum(s);
    float q = warp_sum(s*s);
    if (lane == 0) { rp[warp] = p; rq[warp] = q; }
    __syncthreads();
    if (h == 0) {
        float P = rp[0]+rp[1]+rp[2]+rp[3];
        float Q = rq[0]+rq[1]+rq[2]+rq[3];
        float mu = P * (1.f/HH);
        s_mu = mu;
        s_rstd = rsqrtf(fmaf(-mu, mu, Q * (1.f/HH)) + LN_EPS);
    }
    __syncthreads();

    float m  = fmaf((s - s_mu) * s_rstd, updg[lvl*HH + h], updbe[lvl*HH + h]);
    float xn = us[h] + m;
    g_x[i*HH + h] = xn;
    atomicAdd(&g_lmean[lvl*HH + h], xn * (1.f/NN));
}

// ---------------------------------------------------------------
__global__ void __launch_bounds__(256) k_final(
    const float* __restrict__ fpW, const float* __restrict__ fpb,
    const float* __restrict__ fpg, const float* __restrict__ fpbe,
    float* __restrict__ out)
{
    __shared__ float cs[NLVL*HH];
    __shared__ float rp[8], rq[8];
    __shared__ float s_mu, s_rstd;
    int t = threadIdx.x;
    int warp = t >> 5, lane = t & 31;

    for (int k = t; k < NLVL*HH; k += 256) cs[k] = g_lmean[k];
    __syncthreads();

    float acc = fpb[t];
    #pragma unroll 4
    for (int k = 0; k < NLVL*HH; k++) acc = fmaf(cs[k], fpW[k*DD + t], acc);

    float p = warp_sum(acc);
    float q = warp_sum(acc*acc);
    if (lane == 0) { rp[warp] = p; rq[warp] = q; }
    __syncthreads();
    if (t == 0) {
        float P = 0.f, Q = 0.f;
        #pragma unroll
        for (int w = 0; w < 8; w++) { P += rp[w]; Q += rq[w]; }
        float mu = P * (1.f/DD);
        s_mu = mu;
        s_rstd = rsqrtf(fmaf(-mu, mu, Q * (1.f/DD)) + LN_EPS);
    }
    __syncthreads();

    out[t] = fmaf((acc - s_mu) * s_rstd, fpg[t], fpbe[t]);
}

// ---------------------------------------------------------------
extern "C" void kernel_launch(void* const* d_in, const int* in_sizes, int n_in,
                              void* d_out, int out_size) {
    const int*   an    = (const int*)  d_in[0];
    const float* pos   = (const float*)d_in[1];
    const float* emb   = (const float*)d_in[2];
    const float* deW   = (const float*)d_in[3];
    const float* deb   = (const float*)d_in[4];
    const float* deg   = (const float*)d_in[5];
    const float* debe  = (const float*)d_in[6];
    const float* msgW  = (const float*)d_in[7];
    const float* msgb  = (const float*)d_in[8];
    const float* msgg  = (const float*)d_in[9];
    const float* msgbe = (const float*)d_in[10];
    const float* updW  = (const float*)d_in[11];
    const float* updb  = (const float*)d_in[12];
    const float* updg  = (const float*)d_in[13];
    const float* updbe = (const float*)d_in[14];
    const float* fpW   = (const float*)d_in[15];
    const float* fpb   = (const float*)d_in[16];
    const float* fpg   = (const float*)d_in[17];
    const float* fpbe  = (const float*)d_in[18];
    float* out = (float*)d_out;

    k_init<<<512, 256>>>(an, emb);
    for (int lvl = 0; lvl < NLVL; lvl++) {
        k_preprj<<<128, 128>>>(msgW, msgb, lvl);
        if (lvl == 0)
            k_msum0<<<1024, 256>>>(pos, deW, deb, deg, debe, msgg, msgbe);
        else
            k_msumN<<<1024, 256>>>(msgg, msgbe, lvl);
        k_upd<<<1024, 128>>>(updW, updb, updg, updbe, lvl);
    }
    k_final<<<1, 256>>>(fpW, fpb, fpg, fpbe, out);
}

// round 15
// speedup vs baseline: 1.4098x; 1.0345x over previous
#include <cuda_runtime.h>
#include <cuda_fp16.h>
#include <math.h>

#define NN   1024
#define HH   128
#define DD   256
#define NLVL 3
#define LN_EPS 1e-5f

// -------- device scratch (static: allocation-free kernel_launch) --------
__device__ float g_x[NN*HH];
__device__ float g_pre[NN*HH];
__device__ float g_prj[NN*HH];
__device__ float g_msum[NN*HH];
__device__ float g_esum[NN*HH];     // sum_j ew[i,j,h]  (level-invariant)
__device__ float g_lmean[NLVL*HH];
__device__ __half g_ew[(long long)NN*NN*HH];  // 256 MB fp16, full matrix (mirrored)

// 1-MUFU silu: silu(x) = 0.5*x*(1 + tanh(0.5*x))
__device__ __forceinline__ float silu_f(float x) {
    float t;
    asm("tanh.approx.f32 %0, %1;" : "=f"(t) : "f"(x * 0.5f));
    float hx = 0.5f * x;
    return fmaf(hx, t, hx);
}

__device__ __forceinline__ float warp_sum(float v) {
    #pragma unroll
    for (int off = 16; off; off >>= 1)
        v += __shfl_xor_sync(0xffffffffu, v, off);
    return v;
}

// ---------------------------------------------------------------
__global__ void k_init(const int* __restrict__ an, const float* __restrict__ emb) {
    int t = blockIdx.x * blockDim.x + threadIdx.x;
    if (t < NLVL*HH) g_lmean[t] = 0.f;
    int n = t >> 7;
    int h = t & 127;
    g_x[t] = emb[an[n]*HH + h];
}

// ---------------------------------------------------------------
// ew[i,j,:] = LN(silu(scales @ de_W + de_b))*de_g + de_be  (fp16, mirrored)
// Persistent: 512 blocks; block b covers rows {b, 1023-b}. Weights in regs.
// 16 lanes per pair (8 h each), 2 pairs per warp.
__global__ void __launch_bounds__(256) k_ew(
    const float* __restrict__ pos,
    const float* __restrict__ deW, const float* __restrict__ deb,
    const float* __restrict__ deg, const float* __restrict__ debe)
{
    int warp = threadIdx.x >> 5;
    int lane = threadIdx.x & 31;
    int grp  = lane >> 4;
    int l16  = lane & 15;
    int h0   = l16 << 3;
    int jfix = (warp << 1) + grp;        // 0..15

    float w0[8], w1[8], w2[8], wb[8], wg[8], we[8];
    *(float4*)(w0)   = *(const float4*)(deW + h0);
    *(float4*)(w0+4) = *(const float4*)(deW + h0 + 4);
    *(float4*)(w1)   = *(const float4*)(deW + HH + h0);
    *(float4*)(w1+4) = *(const float4*)(deW + HH + h0 + 4);
    *(float4*)(w2)   = *(const float4*)(deW + 2*HH + h0);
    *(float4*)(w2+4) = *(const float4*)(deW + 2*HH + h0 + 4);
    *(float4*)(wb)   = *(const float4*)(deb + h0);
    *(float4*)(wb+4) = *(const float4*)(deb + h0 + 4);
    *(float4*)(wg)   = *(const float4*)(deg + h0);
    *(float4*)(wg+4) = *(const float4*)(deg + h0 + 4);
    *(float4*)(we)   = *(const float4*)(debe + h0);
    *(float4*)(we+4) = *(const float4*)(debe + h0 + 4);

    #pragma unroll
    for (int half = 0; half < 2; half++) {
        int i = half ? (NN - 1 - (int)blockIdx.x) : (int)blockIdx.x;
        float pix = pos[3*i], piy = pos[3*i+1], piz = pos[3*i+2];

        int nt = (NN - i + 15) >> 4;
        for (int it = 0; it < nt; it++) {
            int j   = i + jfix + (it << 4);
            bool ok = (j < NN);
            int jc  = ok ? j : (NN - 1);

            float dx = pix - pos[3*jc];
            float dy = piy - pos[3*jc+1];
            float dz = piz - pos[3*jc+2];
            float sq = dx*dx + dy*dy + dz*dz;
            float d  = (sq > 0.f) ? sqrtf(sq) : 0.f;
            float s3 = __expf(-0.25f * d);
            float s2 = s3 * s3;
            float s1 = s2 * s2;

            float v[8];
            #pragma unroll
            for (int k = 0; k < 8; k++)
                v[k] = silu_f(fmaf(s1, w0[k], fmaf(s2, w1[k], fmaf(s3, w2[k], wb[k]))));

            float p = ((v[0]+v[1])+(v[2]+v[3])) + ((v[4]+v[5])+(v[6]+v[7]));
            float q = fmaf(v[0],v[0], fmaf(v[1],v[1], fmaf(v[2],v[2], v[3]*v[3])))
                    + fmaf(v[4],v[4], fmaf(v[5],v[5], fmaf(v[6],v[6], v[7]*v[7])));
            #pragma unroll
            for (int off = 8; off; off >>= 1) {
                p += __shfl_xor_sync(0xffffffffu, p, off);
                q += __shfl_xor_sync(0xffffffffu, q, off);
            }
            float mu   = p * (1.f/HH);
            float var  = fmaf(-mu, mu, q * (1.f/HH));
            float rstd = rsqrtf(var + LN_EPS);
            float c0   = -mu * rstd;

            __half2 oh[4];
            #pragma unroll
            for (int k = 0; k < 4; k++) {
                float oa = fmaf(fmaf(v[2*k],   rstd, c0), wg[2*k],   we[2*k]);
                float ob = fmaf(fmaf(v[2*k+1], rstd, c0), wg[2*k+1], we[2*k+1]);
                oh[k] = __floats2half2_rn(oa, ob);
            }
            uint4 pack;
            pack.x = *(unsigned*)&oh[0]; pack.y = *(unsigned*)&oh[1];
            pack.z = *(unsigned*)&oh[2]; pack.w = *(unsigned*)&oh[3];

            if (ok) {
                __stcs((uint4*)(g_ew + ((long long)i*NN + j)*HH + h0), pack);
                if (j != i)
                    __stcs((uint4*)(g_ew + ((long long)j*NN + i)*HH + h0), pack);
            }
        }
    }
}

// ---------------------------------------------------------------
// pre = x@Wi + msg_b, prj = x@Wj.  8 nodes/block, 128 threads (h).
__global__ void __launch_bounds__(128) k_preprj(
    const float* __restrict__ msgW, const float* __restrict__ msgb, int lvl)
{
    __shared__ float xs[8][HH];
    int h  = threadIdx.x;
    int n0 = blockIdx.x << 3;
    #pragma unroll
    for (int nn = 0; nn < 8; nn++) xs[nn][h] = g_x[(n0+nn)*HH + h];
    __syncthreads();

    const float* Wi = msgW + (size_t)lvl*2*HH*HH;
    const float* Wj = Wi + HH*HH;
    float ai[8], aj[8];
    #pragma unroll
    for (int nn = 0; nn < 8; nn++) { ai[nn] = 0.f; aj[nn] = 0.f; }

    for (int k = 0; k < HH; k++) {
        float wi = Wi[k*HH + h];
        float wj = Wj[k*HH + h];
        #pragma unroll
        for (int nn = 0; nn < 8; nn++) {
            ai[nn] = fmaf(xs[nn][k], wi, ai[nn]);
            aj[nn] = fmaf(xs[nn][k], wj, aj[nn]);
        }
    }
    float bb = msgb[lvl*HH + h];
    #pragma unroll
    for (int nn = 0; nn < 8; nn++) {
        g_pre[(n0+nn)*HH + h] = ai[nn] + bb;
        g_prj[(n0+nn)*HH + h] = aj[nn];
    }
}

// ---------------------------------------------------------------
// msum[i,h] = g[h]*sum_j (s-mu)*rstd*e  +  be[h]*sum_j e
// R12-proven: contiguous full-matrix ew reads, compile-time trip counts.
template<bool FIRST>
__global__ void __launch_bounds__(256) k_msum(
    const float* __restrict__ msgg, const float* __restrict__ msgbe, int lvl)
{
    __shared__ float red[16][HH];
    __shared__ float red2[16][HH];
    int i    = blockIdx.x;
    int warp = threadIdx.x >> 5;
    int lane = threadIdx.x & 31;
    int grp  = lane >> 4;
    int l16  = lane & 15;
    int h0   = l16 << 3;

    float pre[8];
    *(float4*)(pre)     = *(const float4*)(g_pre + i*HH + h0);
    *(float4*)(pre + 4) = *(const float4*)(g_pre + i*HH + h0 + 4);

    float a[8] = {0,0,0,0,0,0,0,0};
    float z[8] = {0,0,0,0,0,0,0,0};

    const __half* ewbase = g_ew + (long long)i*NN*HH + h0;
    int jfix = (warp << 1) + grp;

    #pragma unroll 2
    for (int jj = 0; jj < NN/16; jj++) {
        int j = (jj << 4) + jfix;
        float4 pja = *(const float4*)(g_prj + j*HH + h0);
        float4 pjb = *(const float4*)(g_prj + j*HH + h0 + 4);
        uint4  epk = __ldcs((const uint4*)(ewbase + (long long)j*HH));

        float s[8];
        s[0] = silu_f(pre[0] + pja.x);
        s[1] = silu_f(pre[1] + pja.y);
        s[2] = silu_f(pre[2] + pja.z);
        s[3] = silu_f(pre[3] + pja.w);
        s[4] = silu_f(pre[4] + pjb.x);
        s[5] = silu_f(pre[5] + pjb.y);
        s[6] = silu_f(pre[6] + pjb.z);
        s[7] = silu_f(pre[7] + pjb.w);

        float p = ((s[0]+s[1])+(s[2]+s[3])) + ((s[4]+s[5])+(s[6]+s[7]));
        float q = fmaf(s[0],s[0], fmaf(s[1],s[1], fmaf(s[2],s[2], s[3]*s[3])))
                + fmaf(s[4],s[4], fmaf(s[5],s[5], fmaf(s[6],s[6], s[7]*s[7])));
        #pragma unroll
        for (int off = 8; off; off >>= 1) {
            p += __shfl_xor_sync(0xffffffffu, p, off);
            q += __shfl_xor_sync(0xffffffffu, q, off);
        }
        float mu   = p * (1.f/HH);
        float var  = fmaf(-mu, mu, q * (1.f/HH));
        float rstd = rsqrtf(var + LN_EPS);
        float c0   = -mu * rstd;

        unsigned u0 = epk.x, u1 = epk.y, u2 = epk.z, u3 = epk.w;
        float2 f0 = __half22float2(*(__half2*)&u0);
        float2 f1 = __half22float2(*(__half2*)&u1);
        float2 f2 = __half22float2(*(__half2*)&u2);
        float2 f3 = __half22float2(*(__half2*)&u3);
        float e[8] = { f0.x, f0.y, f1.x, f1.y, f2.x, f2.y, f3.x, f3.y };

        #pragma unroll
        for (int k = 0; k < 8; k++) {
            a[k] = fmaf(fmaf(s[k], rstd, c0), e[k], a[k]);
            if (FIRST) z[k] += e[k];
        }
    }

    int slot = (warp << 1) | grp;
    #pragma unroll
    for (int k = 0; k < 8; k++) red[slot][h0+k] = a[k];
    if (FIRST) {
        #pragma unroll
        for (int k = 0; k < 8; k++) red2[slot][h0+k] = z[k];
    }
    __syncthreads();
    if (threadIdx.x < HH) {
        int h = threadIdx.x;
        float S1 = 0.f, S0 = 0.f;
        #pragma unroll
        for (int w = 0; w < 16; w++) S1 += red[w][h];
        if (FIRST) {
            #pragma unroll
            for (int w = 0; w < 16; w++) S0 += red2[w][h];
            g_esum[i*HH + h] = S0;
        } else {
            S0 = g_esum[i*HH + h];
        }
        g_msum[i*HH + h] = fmaf(msgg[lvl*HH + h], S1, msgbe[lvl*HH + h] * S0);
    }
}

// ---------------------------------------------------------------
// x += LN(silu([x, msum] @ upd_W + upd_b)); accumulate level mean.
// REWRITTEN: 8 nodes per block (k_preprj style) -> 8-way ILP on the GEMM.
// grid 128, block 128 (h).
__global__ void __launch_bounds__(128) k_upd(
    const float* __restrict__ updW, const float* __restrict__ updb,
    const float* __restrict__ updg, const float* __restrict__ updbe, int lvl)
{
    __shared__ float us[8][2*HH];     // [node][x | msum]
    __shared__ float sv[8][HH];       // silu values for LN reduction
    __shared__ float smu[8], srs[8];
    int h  = threadIdx.x;
    int n0 = blockIdx.x << 3;
    int warp = h >> 5, lane = h & 31;

    #pragma unroll
    for (int nn = 0; nn < 8; nn++) {
        us[nn][h]      = g_x[(n0+nn)*HH + h];
        us[nn][HH + h] = g_msum[(n0+nn)*HH + h];
    }
    __syncthreads();

    const float* W = updW + (size_t)lvl*2*HH*HH;
    float bb = updb[lvl*HH + h];
    float acc[8];
    #pragma unroll
    for (int nn = 0; nn < 8; nn++) acc[nn] = bb;

    for (int k = 0; k < 2*HH; k++) {
        float w = W[k*HH + h];
        #pragma unroll
        for (int nn = 0; nn < 8; nn++)
            acc[nn] = fmaf(us[nn][k], w, acc[nn]);
    }

    float sl[8];
    #pragma unroll
    for (int nn = 0; nn < 8; nn++) {
        sl[nn] = silu_f(acc[nn]);
        sv[nn][h] = sl[nn];
    }
    __syncthreads();

    // each warp reduces 2 nodes (128 values each: 4 per lane + butterfly)
    #pragma unroll
    for (int t = 0; t < 2; t++) {
        int nn = (warp << 1) + t;
        float v0 = sv[nn][lane], v1 = sv[nn][lane+32];
        float v2 = sv[nn][lane+64], v3 = sv[nn][lane+96];
        float p = (v0+v1) + (v2+v3);
        float q = fmaf(v0,v0, fmaf(v1,v1, fmaf(v2,v2, v3*v3)));
        #pragma unroll
        for (int off = 16; off; off >>= 1) {
            p += __shfl_xor_sync(0xffffffffu, p, off);
            q += __shfl_xor_sync(0xffffffffu, q, off);
        }
        if (lane == 0) {
            float mu = p * (1.f/HH);
            smu[nn] = mu;
            srs[nn] = rsqrtf(fmaf(-mu, mu, q * (1.f/HH)) + LN_EPS);
        }
    }
    __syncthreads();

    float gg = updg[lvl*HH + h], be = updbe[lvl*HH + h];
    float lm = 0.f;
    #pragma unroll
    for (int nn = 0; nn < 8; nn++) {
        float m  = fmaf((sl[nn] - smu[nn]) * srs[nn], gg, be);
        float xn = us[nn][h] + m;
        g_x[(n0+nn)*HH + h] = xn;
        lm += xn;
    }
    atomicAdd(&g_lmean[lvl*HH + h], lm * (1.f/NN));
}

// ---------------------------------------------------------------
__global__ void __launch_bounds__(256) k_final(
    const float* __restrict__ fpW, const float* __restrict__ fpb,
    const float* __restrict__ fpg, const float* __restrict__ fpbe,
    float* __restrict__ out)
{
    __shared__ float cs[NLVL*HH];
    __shared__ float rp[8], rq[8];
    __shared__ float s_mu, s_rstd;
    int t = threadIdx.x;
    int warp = t >> 5, lane = t & 31;

    for (int k = t; k < NLVL*HH; k += 256) cs[k] = g_lmean[k];
    __syncthreads();

    float acc = fpb[t];
    #pragma unroll 4
    for (int k = 0; k < NLVL*HH; k++) acc = fmaf(cs[k], fpW[k*DD + t], acc);

    float p = warp_sum(acc);
    float q = warp_sum(acc*acc);
    if (lane == 0) { rp[warp] = p; rq[warp] = q; }
    __syncthreads();
    if (t == 0) {
        float P = 0.f, Q = 0.f;
        #pragma unroll
        for (int w = 0; w < 8; w++) { P += rp[w]; Q += rq[w]; }
        float mu = P * (1.f/DD);
        s_mu = mu;
        s_rstd = rsqrtf(fmaf(-mu, mu, Q * (1.f/DD)) + LN_EPS);
    }
    __syncthreads();

    out[t] = fmaf((acc - s_mu) * s_rstd, fpg[t], fpbe[t]);
}

// ---------------------------------------------------------------
extern "C" void kernel_launch(void* const* d_in, const int* in_sizes, int n_in,
                              void* d_out, int out_size) {
    const int*   an    = (const int*)  d_in[0];
    const float* pos   = (const float*)d_in[1];
    const float* emb   = (const float*)d_in[2];
    const float* deW   = (const float*)d_in[3];
    const float* deb   = (const float*)d_in[4];
    const float* deg   = (const float*)d_in[5];
    const float* debe  = (const float*)d_in[6];
    const float* msgW  = (const float*)d_in[7];
    const float* msgb  = (const float*)d_in[8];
    const float* msgg  = (const float*)d_in[9];
    const float* msgbe = (const float*)d_in[10];
    const float* updW  = (const float*)d_in[11];
    const float* updb  = (const float*)d_in[12];
    const float* updg  = (const float*)d_in[13];
    const float* updbe = (const float*)d_in[14];
    const float* fpW   = (const float*)d_in[15];
    const float* fpb   = (const float*)d_in[16];
    const float* fpg   = (const float*)d_in[17];
    const float* fpbe  = (const float*)d_in[18];
    float* out = (float*)d_out;

    k_init<<<512, 256>>>(an, emb);
    k_ew<<<512, 256>>>(pos, deW, deb, deg, debe);
    for (int lvl = 0; lvl < NLVL; lvl++) {
        k_preprj<<<128, 128>>>(msgW, msgb, lvl);
        if (lvl == 0) k_msum<true><<<1024, 256>>>(msgg, msgbe, lvl);
        else          k_msum<false><<<1024, 256>>>(msgg, msgbe, lvl);
        k_upd<<<128, 128>>>(updW, updb, updg, updbe, lvl);
    }
    k_final<<<1, 256>>>(fpW, fpb, fpg, fpbe, out);
}

// round 16
// speedup vs baseline: 1.7104x; 1.2132x over previous
#include <cuda_runtime.h>
#include <cuda_fp16.h>
#include <math.h>

#define NN   1024
#define HH   128
#define DD   256
#define NLVL 3
#define LN_EPS 1e-5f
#define TGRID 4096
#define DMAX  32.0f
#define TINVD ((float)TGRID / DMAX)     // 128.0

// -------- device scratch (static: allocation-free kernel_launch) --------
__device__ float g_x[NN*HH];
__device__ float g_pre[NN*HH];
__device__ float g_prj[NN*HH];
__device__ float g_msum[NN*HH];
__device__ float g_esum[NN*HH];     // sum_j ew[i,j,h]  (level-invariant)
__device__ float g_lmean[NLVL*HH];
__device__ __half g_tab[TGRID*HH];  // 1MB: ew as a function of distance

// 1-MUFU silu: silu(x) = 0.5*x*(1 + tanh(0.5*x))
__device__ __forceinline__ float silu_f(float x) {
    float t;
    asm("tanh.approx.f32 %0, %1;" : "=f"(t) : "f"(x * 0.5f));
    float hx = 0.5f * x;
    return fmaf(hx, t, hx);
}

__device__ __forceinline__ float warp_sum(float v) {
    #pragma unroll
    for (int off = 16; off; off >>= 1)
        v += __shfl_xor_sync(0xffffffffu, v, off);
    return v;
}

// ---------------------------------------------------------------
__global__ void k_init(const int* __restrict__ an, const float* __restrict__ emb) {
    int t = blockIdx.x * blockDim.x + threadIdx.x;
    if (t < NLVL*HH) g_lmean[t] = 0.f;
    int n = t >> 7;
    int h = t & 127;
    g_x[t] = emb[an[n]*HH + h];
}

// ---------------------------------------------------------------
// Build the distance->ew table. One warp per grid point, 4 h per lane.
// Precise math (one-off, 4096 points): expf + exact silu.
__global__ void __launch_bounds__(256) k_tab(
    const float* __restrict__ deW, const float* __restrict__ deb,
    const float* __restrict__ deg, const float* __restrict__ debe)
{
    int warp = threadIdx.x >> 5;
    int lane = threadIdx.x & 31;
    int p = (blockIdx.x << 3) + warp;     // 0..4095
    float d = (float)p * (DMAX / (float)TGRID);
    float s1 = expf(-d);
    float s2 = expf(-0.5f * d);
    float s3 = expf(-0.25f * d);

    int h0 = lane << 2;
    float4 w0 = *(const float4*)(deW + h0);
    float4 w1 = *(const float4*)(deW + HH + h0);
    float4 w2 = *(const float4*)(deW + 2*HH + h0);
    float4 bb = *(const float4*)(deb + h0);

    float v0 = fmaf(s1, w0.x, fmaf(s2, w1.x, fmaf(s3, w2.x, bb.x)));
    float v1 = fmaf(s1, w0.y, fmaf(s2, w1.y, fmaf(s3, w2.y, bb.y)));
    float v2 = fmaf(s1, w0.z, fmaf(s2, w1.z, fmaf(s3, w2.z, bb.z)));
    float v3 = fmaf(s1, w0.w, fmaf(s2, w1.w, fmaf(s3, w2.w, bb.w)));

    v0 = v0 / (1.f + expf(-v0));
    v1 = v1 / (1.f + expf(-v1));
    v2 = v2 / (1.f + expf(-v2));
    v3 = v3 / (1.f + expf(-v3));

    float pacc = warp_sum(v0 + v1 + v2 + v3);
    float qacc = warp_sum(fmaf(v0,v0, fmaf(v1,v1, fmaf(v2,v2, v3*v3))));
    float mu   = pacc * (1.f/HH);
    float var  = fmaf(-mu, mu, qacc * (1.f/HH));
    float rstd = rsqrtf(var + LN_EPS);

    float4 gg = *(const float4*)(deg + h0);
    float4 be = *(const float4*)(debe + h0);
    float o0 = fmaf((v0 - mu) * rstd, gg.x, be.x);
    float o1 = fmaf((v1 - mu) * rstd, gg.y, be.y);
    float o2 = fmaf((v2 - mu) * rstd, gg.z, be.z);
    float o3 = fmaf((v3 - mu) * rstd, gg.w, be.w);

    __half2* dst = (__half2*)(g_tab + p*HH + h0);
    dst[0] = __floats2half2_rn(o0, o1);
    dst[1] = __floats2half2_rn(o2, o3);
}

// ---------------------------------------------------------------
// pre = x@Wi + msg_b, prj = x@Wj.  8 nodes/block, 128 threads (h).
__global__ void __launch_bounds__(128) k_preprj(
    const float* __restrict__ msgW, const float* __restrict__ msgb, int lvl)
{
    __shared__ float xs[8][HH];
    int h  = threadIdx.x;
    int n0 = blockIdx.x << 3;
    #pragma unroll
    for (int nn = 0; nn < 8; nn++) xs[nn][h] = g_x[(n0+nn)*HH + h];
    __syncthreads();

    const float* Wi = msgW + (size_t)lvl*2*HH*HH;
    const float* Wj = Wi + HH*HH;
    float ai[8], aj[8];
    #pragma unroll
    for (int nn = 0; nn < 8; nn++) { ai[nn] = 0.f; aj[nn] = 0.f; }

    for (int k = 0; k < HH; k++) {
        float wi = Wi[k*HH + h];
        float wj = Wj[k*HH + h];
        #pragma unroll
        for (int nn = 0; nn < 8; nn++) {
            ai[nn] = fmaf(xs[nn][k], wi, ai[nn]);
            aj[nn] = fmaf(xs[nn][k], wj, aj[nn]);
        }
    }
    float bb = msgb[lvl*HH + h];
    #pragma unroll
    for (int nn = 0; nn < 8; nn++) {
        g_pre[(n0+nn)*HH + h] = ai[nn] + bb;
        g_prj[(n0+nn)*HH + h] = aj[nn];
    }
}

// ---------------------------------------------------------------
// msum[i,h] = g[h]*sum_j (s-mu)*rstd*e + be[h]*sum_j e,  e = lerp(g_tab, d_ij)
// 16 lanes per j (8 h each), 2 j per warp; table gathered from L1/L2.
template<bool FIRST>
__global__ void __launch_bounds__(256) k_msum(
    const float* __restrict__ pos,
    const float* __restrict__ msgg, const float* __restrict__ msgbe, int lvl)
{
    __shared__ float red[16][HH];
    __shared__ float red2[16][HH];
    __shared__ float s_u[NN];
    int i    = blockIdx.x;
    int warp = threadIdx.x >> 5;
    int lane = threadIdx.x & 31;
    int grp  = lane >> 4;
    int l16  = lane & 15;
    int h0   = l16 << 3;

    // prologue: lookup coordinates for all j
    {
        float pix = pos[3*i], piy = pos[3*i+1], piz = pos[3*i+2];
        for (int j = threadIdx.x; j < NN; j += 256) {
            float dx = pix - pos[3*j];
            float dy = piy - pos[3*j+1];
            float dz = piz - pos[3*j+2];
            float sq = dx*dx + dy*dy + dz*dz;
            float d  = (sq > 0.f) ? sqrtf(sq) : 0.f;
            s_u[j] = fminf(d * TINVD, (float)(TGRID-2) + 0.999f);
        }
    }
    __syncthreads();

    float pre[8];
    *(float4*)(pre)     = *(const float4*)(g_pre + i*HH + h0);
    *(float4*)(pre + 4) = *(const float4*)(g_pre + i*HH + h0 + 4);

    float a[8] = {0,0,0,0,0,0,0,0};
    float z[8] = {0,0,0,0,0,0,0,0};
    int jfix = (warp << 1) + grp;

    #pragma unroll 2
    for (int jj = 0; jj < NN/16; jj++) {
        int j = (jj << 4) + jfix;
        float4 pja = *(const float4*)(g_prj + j*HH + h0);
        float4 pjb = *(const float4*)(g_prj + j*HH + h0 + 4);

        float u  = s_u[j];
        int   iu = (int)u;
        float fr = u - (float)iu;
        const __half* tb = g_tab + iu*HH + h0;
        uint4 ta = *(const uint4*)(tb);
        uint4 tc = *(const uint4*)(tb + HH);

        float s[8];
        s[0] = silu_f(pre[0] + pja.x);
        s[1] = silu_f(pre[1] + pja.y);
        s[2] = silu_f(pre[2] + pja.z);
        s[3] = silu_f(pre[3] + pja.w);
        s[4] = silu_f(pre[4] + pjb.x);
        s[5] = silu_f(pre[5] + pjb.y);
        s[6] = silu_f(pre[6] + pjb.z);
        s[7] = silu_f(pre[7] + pjb.w);

        float p = ((s[0]+s[1])+(s[2]+s[3])) + ((s[4]+s[5])+(s[6]+s[7]));
        float q = fmaf(s[0],s[0], fmaf(s[1],s[1], fmaf(s[2],s[2], s[3]*s[3])))
                + fmaf(s[4],s[4], fmaf(s[5],s[5], fmaf(s[6],s[6], s[7]*s[7])));
        #pragma unroll
        for (int off = 8; off; off >>= 1) {
            p += __shfl_xor_sync(0xffffffffu, p, off);
            q += __shfl_xor_sync(0xffffffffu, q, off);
        }
        float mu   = p * (1.f/HH);
        float var  = fmaf(-mu, mu, q * (1.f/HH));
        float rstd = rsqrtf(var + LN_EPS);
        float c0   = -mu * rstd;

        // half2 lerp of the two table rows
        __half2 hfr = __float2half2_rn(fr);
        float e[8];
        {
            unsigned ua[4] = { ta.x, ta.y, ta.z, ta.w };
            unsigned uc[4] = { tc.x, tc.y, tc.z, tc.w };
            #pragma unroll
            for (int k = 0; k < 4; k++) {
                __half2 h0v = *(__half2*)&ua[k];
                __half2 h1v = *(__half2*)&uc[k];
                __half2 r   = __hfma2(__hsub2(h1v, h0v), hfr, h0v);
                float2 f = __half22float2(r);
                e[2*k]   = f.x;
                e[2*k+1] = f.y;
            }
        }

        #pragma unroll
        for (int k = 0; k < 8; k++) {
            a[k] = fmaf(fmaf(s[k], rstd, c0), e[k], a[k]);
            if (FIRST) z[k] += e[k];
        }
    }

    int slot = (warp << 1) | grp;
    #pragma unroll
    for (int k = 0; k < 8; k++) red[slot][h0+k] = a[k];
    if (FIRST) {
        #pragma unroll
        for (int k = 0; k < 8; k++) red2[slot][h0+k] = z[k];
    }
    __syncthreads();
    if (threadIdx.x < HH) {
        int h = threadIdx.x;
        float S1 = 0.f, S0 = 0.f;
        #pragma unroll
        for (int w = 0; w < 16; w++) S1 += red[w][h];
        if (FIRST) {
            #pragma unroll
            for (int w = 0; w < 16; w++) S0 += red2[w][h];
            g_esum[i*HH + h] = S0;
        } else {
            S0 = g_esum[i*HH + h];
        }
        g_msum[i*HH + h] = fmaf(msgg[lvl*HH + h], S1, msgbe[lvl*HH + h] * S0);
    }
}

// ---------------------------------------------------------------
// x += LN(silu([x, msum] @ upd_W + upd_b)); accumulate level mean.
// 8 nodes per block, 8-way ILP on the GEMM.
__global__ void __launch_bounds__(128) k_upd(
    const float* __restrict__ updW, const float* __restrict__ updb,
    const float* __restrict__ updg, const float* __restrict__ updbe, int lvl)
{
    __shared__ float us[8][2*HH];
    __shared__ float sv[8][HH];
    __shared__ float smu[8], srs[8];
    int h  = threadIdx.x;
    int n0 = blockIdx.x << 3;
    int warp = h >> 5, lane = h & 31;

    #pragma unroll
    for (int nn = 0; nn < 8; nn++) {
        us[nn][h]      = g_x[(n0+nn)*HH + h];
        us[nn][HH + h] = g_msum[(n0+nn)*HH + h];
    }
    __syncthreads();

    const float* W = updW + (size_t)lvl*2*HH*HH;
    float bb = updb[lvl*HH + h];
    float acc[8];
    #pragma unroll
    for (int nn = 0; nn < 8; nn++) acc[nn] = bb;

    for (int k = 0; k < 2*HH; k++) {
        float w = W[k*HH + h];
        #pragma unroll
        for (int nn = 0; nn < 8; nn++)
            acc[nn] = fmaf(us[nn][k], w, acc[nn]);
    }

    float sl[8];
    #pragma unroll
    for (int nn = 0; nn < 8; nn++) {
        sl[nn] = silu_f(acc[nn]);
        sv[nn][h] = sl[nn];
    }
    __syncthreads();

    #pragma unroll
    for (int t = 0; t < 2; t++) {
        int nn = (warp << 1) + t;
        float v0 = sv[nn][lane], v1 = sv[nn][lane+32];
        float v2 = sv[nn][lane+64], v3 = sv[nn][lane+96];
        float p = (v0+v1) + (v2+v3);
        float q = fmaf(v0,v0, fmaf(v1,v1, fmaf(v2,v2, v3*v3)));
        #pragma unroll
        for (int off = 16; off; off >>= 1) {
            p += __shfl_xor_sync(0xffffffffu, p, off);
            q += __shfl_xor_sync(0xffffffffu, q, off);
        }
        if (lane == 0) {
            float mu = p * (1.f/HH);
            smu[nn] = mu;
            srs[nn] = rsqrtf(fmaf(-mu, mu, q * (1.f/HH)) + LN_EPS);
        }
    }
    __syncthreads();

    float gg = updg[lvl*HH + h], be = updbe[lvl*HH + h];
    float lm = 0.f;
    #pragma unroll
    for (int nn = 0; nn < 8; nn++) {
        float m  = fmaf((sl[nn] - smu[nn]) * srs[nn], gg, be);
        float xn = us[nn][h] + m;
        g_x[(n0+nn)*HH + h] = xn;
        lm += xn;
    }
    atomicAdd(&g_lmean[lvl*HH + h], lm * (1.f/NN));
}

// ---------------------------------------------------------------
__global__ void __launch_bounds__(256) k_final(
    const float* __restrict__ fpW, const float* __restrict__ fpb,
    const float* __restrict__ fpg, const float* __restrict__ fpbe,
    float* __restrict__ out)
{
    __shared__ float cs[NLVL*HH];
    __shared__ float rp[8], rq[8];
    __shared__ float s_mu, s_rstd;
    int t = threadIdx.x;
    int warp = t >> 5, lane = t & 31;

    for (int k = t; k < NLVL*HH; k += 256) cs[k] = g_lmean[k];
    __syncthreads();

    float acc = fpb[t];
    #pragma unroll 4
    for (int k = 0; k < NLVL*HH; k++) acc = fmaf(cs[k], fpW[k*DD + t], acc);

    float p = warp_sum(acc);
    float q = warp_sum(acc*acc);
    if (lane == 0) { rp[warp] = p; rq[warp] = q; }
    __syncthreads();
    if (t == 0) {
        float P = 0.f, Q = 0.f;
        #pragma unroll
        for (int w = 0; w < 8; w++) { P += rp[w]; Q += rq[w]; }
        float mu = P * (1.f/DD);
        s_mu = mu;
        s_rstd = rsqrtf(fmaf(-mu, mu, Q * (1.f/DD)) + LN_EPS);
    }
    __syncthreads();

    out[t] = fmaf((acc - s_mu) * s_rstd, fpg[t], fpbe[t]);
}

// ---------------------------------------------------------------
extern "C" void kernel_launch(void* const* d_in, const int* in_sizes, int n_in,
                              void* d_out, int out_size) {
    const int*   an    = (const int*)  d_in[0];
    const float* pos   = (const float*)d_in[1];
    const float* emb   = (const float*)d_in[2];
    const float* deW   = (const float*)d_in[3];
    const float* deb   = (const float*)d_in[4];
    const float* deg   = (const float*)d_in[5];
    const float* debe  = (const float*)d_in[6];
    const float* msgW  = (const float*)d_in[7];
    const float* msgb  = (const float*)d_in[8];
    const float* msgg  = (const float*)d_in[9];
    const float* msgbe = (const float*)d_in[10];
    const float* updW  = (const float*)d_in[11];
    const float* updb  = (const float*)d_in[12];
    const float* updg  = (const float*)d_in[13];
    const float* updbe = (const float*)d_in[14];
    const float* fpW   = (const float*)d_in[15];
    const float* fpb   = (const float*)d_in[16];
    const float* fpg   = (const float*)d_in[17];
    const float* fpbe  = (const float*)d_in[18];
    float* out = (float*)d_out;

    k_init<<<512, 256>>>(an, emb);
    k_tab<<<512, 256>>>(deW, deb, deg, debe);
    for (int lvl = 0; lvl < NLVL; lvl++) {
        k_preprj<<<128, 128>>>(msgW, msgb, lvl);
        if (lvl == 0) k_msum<true><<<1024, 256>>>(pos, msgg, msgbe, lvl);
        else          k_msum<false><<<1024, 256>>>(pos, msgg, msgbe, lvl);
        k_upd<<<128, 128>>>(updW, updb, updg, updbe, lvl);
    }
    k_final<<<1, 256>>>(fpW, fpb, fpg, fpbe, out);
}

// round 17
// speedup vs baseline: 1.7179x; 1.0044x over previous
#include <cuda_runtime.h>
#include <cuda_fp16.h>
#include <math.h>

#define NN   1024
#define HH   128
#define DD   256
#define NLVL 3
#define LN_EPS 1e-5f
#define TGRID 65536
#define DMAX  32.0f
#define TINVD ((float)TGRID / DMAX)     // 2048.0

// -------- device scratch (static: allocation-free kernel_launch) --------
__device__ float g_x[NN*HH];
__device__ float g_pre[NN*HH];
__device__ float g_prj[NN*HH];
__device__ float g_msum[NN*HH];
__device__ float g_esum[NN*HH];     // sum_j ew[i,j,h]  (level-invariant)
__device__ float g_lmean[NLVL*HH];
__device__ __half g_tab[(long long)TGRID*HH];  // 16MB: ew(d), nearest-neighbor grid

// 1-MUFU silu: silu(x) = 0.5*x*(1 + tanh(0.5*x))
__device__ __forceinline__ float silu_f(float x) {
    float t;
    asm("tanh.approx.f32 %0, %1;" : "=f"(t) : "f"(x * 0.5f));
    float hx = 0.5f * x;
    return fmaf(hx, t, hx);
}

__device__ __forceinline__ float warp_sum(float v) {
    #pragma unroll
    for (int off = 16; off; off >>= 1)
        v += __shfl_xor_sync(0xffffffffu, v, off);
    return v;
}

// ---------------------------------------------------------------
__global__ void k_init(const int* __restrict__ an, const float* __restrict__ emb) {
    int t = blockIdx.x * blockDim.x + threadIdx.x;
    if (t < NLVL*HH) g_lmean[t] = 0.f;
    int n = t >> 7;
    int h = t & 127;
    g_x[t] = emb[an[n]*HH + h];
}

// ---------------------------------------------------------------
// Build the distance->ew table. One warp per grid point, 4 h per lane.
// Precise math (one-off): expf + exact silu.
__global__ void __launch_bounds__(256) k_tab(
    const float* __restrict__ deW, const float* __restrict__ deb,
    const float* __restrict__ deg, const float* __restrict__ debe)
{
    int warp = threadIdx.x >> 5;
    int lane = threadIdx.x & 31;
    int p = (blockIdx.x << 3) + warp;     // 0..TGRID-1
    float d = (float)p * (DMAX / (float)TGRID);
    float s1 = expf(-d);
    float s2 = expf(-0.5f * d);
    float s3 = expf(-0.25f * d);

    int h0 = lane << 2;
    float4 w0 = *(const float4*)(deW + h0);
    float4 w1 = *(const float4*)(deW + HH + h0);
    float4 w2 = *(const float4*)(deW + 2*HH + h0);
    float4 bb = *(const float4*)(deb + h0);

    float v0 = fmaf(s1, w0.x, fmaf(s2, w1.x, fmaf(s3, w2.x, bb.x)));
    float v1 = fmaf(s1, w0.y, fmaf(s2, w1.y, fmaf(s3, w2.y, bb.y)));
    float v2 = fmaf(s1, w0.z, fmaf(s2, w1.z, fmaf(s3, w2.z, bb.z)));
    float v3 = fmaf(s1, w0.w, fmaf(s2, w1.w, fmaf(s3, w2.w, bb.w)));

    v0 = v0 / (1.f + expf(-v0));
    v1 = v1 / (1.f + expf(-v1));
    v2 = v2 / (1.f + expf(-v2));
    v3 = v3 / (1.f + expf(-v3));

    float pacc = warp_sum(v0 + v1 + v2 + v3);
    float qacc = warp_sum(fmaf(v0,v0, fmaf(v1,v1, fmaf(v2,v2, v3*v3))));
    float mu   = pacc * (1.f/HH);
    float var  = fmaf(-mu, mu, qacc * (1.f/HH));
    float rstd = rsqrtf(var + LN_EPS);

    float4 gg = *(const float4*)(deg + h0);
    float4 be = *(const float4*)(debe + h0);
    float o0 = fmaf((v0 - mu) * rstd, gg.x, be.x);
    float o1 = fmaf((v1 - mu) * rstd, gg.y, be.y);
    float o2 = fmaf((v2 - mu) * rstd, gg.z, be.z);
    float o3 = fmaf((v3 - mu) * rstd, gg.w, be.w);

    __half2* dst = (__half2*)(g_tab + (long long)p*HH + h0);
    dst[0] = __floats2half2_rn(o0, o1);
    dst[1] = __floats2half2_rn(o2, o3);
}

// ---------------------------------------------------------------
// pre = x@Wi + msg_b, prj = x@Wj.  8 nodes/block, 128 threads (h).
__global__ void __launch_bounds__(128) k_preprj(
    const float* __restrict__ msgW, const float* __restrict__ msgb, int lvl)
{
    __shared__ float xs[8][HH];
    int h  = threadIdx.x;
    int n0 = blockIdx.x << 3;
    #pragma unroll
    for (int nn = 0; nn < 8; nn++) xs[nn][h] = g_x[(n0+nn)*HH + h];
    __syncthreads();

    const float* Wi = msgW + (size_t)lvl*2*HH*HH;
    const float* Wj = Wi + HH*HH;
    float ai[8], aj[8];
    #pragma unroll
    for (int nn = 0; nn < 8; nn++) { ai[nn] = 0.f; aj[nn] = 0.f; }

    for (int k = 0; k < HH; k++) {
        float wi = Wi[k*HH + h];
        float wj = Wj[k*HH + h];
        #pragma unroll
        for (int nn = 0; nn < 8; nn++) {
            ai[nn] = fmaf(xs[nn][k], wi, ai[nn]);
            aj[nn] = fmaf(xs[nn][k], wj, aj[nn]);
        }
    }
    float bb = msgb[lvl*HH + h];
    #pragma unroll
    for (int nn = 0; nn < 8; nn++) {
        g_pre[(n0+nn)*HH + h] = ai[nn] + bb;
        g_prj[(n0+nn)*HH + h] = aj[nn];
    }
}

// ---------------------------------------------------------------
// msum[i,h] = g[h]*sum_j (s-mu)*rstd*e + be[h]*sum_j e,
// e = g_tab[round(d_ij * TINVD)]  (nearest-neighbor; table L2-resident)
// 16 lanes per j (8 h each), 2 j per warp.
template<bool FIRST>
__global__ void __launch_bounds__(256) k_msum(
    const float* __restrict__ pos,
    const float* __restrict__ msgg, const float* __restrict__ msgbe, int lvl)
{
    __shared__ float red[16][HH];
    __shared__ float red2[16][HH];
    __shared__ int   s_iu[NN];
    int i    = blockIdx.x;
    int warp = threadIdx.x >> 5;
    int lane = threadIdx.x & 31;
    int grp  = lane >> 4;
    int l16  = lane & 15;
    int h0   = l16 << 3;

    // prologue: nearest table row index for all j
    {
        float pix = pos[3*i], piy = pos[3*i+1], piz = pos[3*i+2];
        for (int j = threadIdx.x; j < NN; j += 256) {
            float dx = pix - pos[3*j];
            float dy = piy - pos[3*j+1];
            float dz = piz - pos[3*j+2];
            float sq = dx*dx + dy*dy + dz*dz;
            float d  = (sq > 0.f) ? sqrtf(sq) : 0.f;
            int iu = __float2int_rn(d * TINVD);
            s_iu[j] = iu < TGRID-1 ? iu : TGRID-1;
        }
    }
    __syncthreads();

    float pre[8];
    *(float4*)(pre)     = *(const float4*)(g_pre + i*HH + h0);
    *(float4*)(pre + 4) = *(const float4*)(g_pre + i*HH + h0 + 4);

    float a[8] = {0,0,0,0,0,0,0,0};
    float z[8] = {0,0,0,0,0,0,0,0};
    int jfix = (warp << 1) + grp;

    #pragma unroll 2
    for (int jj = 0; jj < NN/16; jj++) {
        int j = (jj << 4) + jfix;
        float4 pja = *(const float4*)(g_prj + j*HH + h0);
        float4 pjb = *(const float4*)(g_prj + j*HH + h0 + 4);

        int iu = s_iu[j];
        uint4 ta = *(const uint4*)(g_tab + (long long)iu*HH + h0);

        float s[8];
        s[0] = silu_f(pre[0] + pja.x);
        s[1] = silu_f(pre[1] + pja.y);
        s[2] = silu_f(pre[2] + pja.z);
        s[3] = silu_f(pre[3] + pja.w);
        s[4] = silu_f(pre[4] + pjb.x);
        s[5] = silu_f(pre[5] + pjb.y);
        s[6] = silu_f(pre[6] + pjb.z);
        s[7] = silu_f(pre[7] + pjb.w);

        float p = ((s[0]+s[1])+(s[2]+s[3])) + ((s[4]+s[5])+(s[6]+s[7]));
        float q = fmaf(s[0],s[0], fmaf(s[1],s[1], fmaf(s[2],s[2], s[3]*s[3])))
                + fmaf(s[4],s[4], fmaf(s[5],s[5], fmaf(s[6],s[6], s[7]*s[7])));
        #pragma unroll
        for (int off = 8; off; off >>= 1) {
            p += __shfl_xor_sync(0xffffffffu, p, off);
            q += __shfl_xor_sync(0xffffffffu, q, off);
        }
        float mu   = p * (1.f/HH);
        float var  = fmaf(-mu, mu, q * (1.f/HH));
        float rstd = rsqrtf(var + LN_EPS);
        float c0   = -mu * rstd;

        unsigned u0 = ta.x, u1 = ta.y, u2 = ta.z, u3 = ta.w;
        float2 f0 = __half22float2(*(__half2*)&u0);
        float2 f1 = __half22float2(*(__half2*)&u1);
        float2 f2 = __half22float2(*(__half2*)&u2);
        float2 f3 = __half22float2(*(__half2*)&u3);
        float e[8] = { f0.x, f0.y, f1.x, f1.y, f2.x, f2.y, f3.x, f3.y };

        #pragma unroll
        for (int k = 0; k < 8; k++) {
            a[k] = fmaf(fmaf(s[k], rstd, c0), e[k], a[k]);
            if (FIRST) z[k] += e[k];
        }
    }

    int slot = (warp << 1) | grp;
    #pragma unroll
    for (int k = 0; k < 8; k++) red[slot][h0+k] = a[k];
    if (FIRST) {
        #pragma unroll
        for (int k = 0; k < 8; k++) red2[slot][h0+k] = z[k];
    }
    __syncthreads();
    if (threadIdx.x < HH) {
        int h = threadIdx.x;
        float S1 = 0.f, S0 = 0.f;
        #pragma unroll
        for (int w = 0; w < 16; w++) S1 += red[w][h];
        if (FIRST) {
            #pragma unroll
            for (int w = 0; w < 16; w++) S0 += red2[w][h];
            g_esum[i*HH + h] = S0;
        } else {
            S0 = g_esum[i*HH + h];
        }
        g_msum[i*HH + h] = fmaf(msgg[lvl*HH + h], S1, msgbe[lvl*HH + h] * S0);
    }
}

// ---------------------------------------------------------------
// x += LN(silu([x, msum] @ upd_W + upd_b)); accumulate level mean.
// 8 nodes per block, 8-way ILP on the GEMM.
__global__ void __launch_bounds__(128) k_upd(
    const float* __restrict__ updW, const float* __restrict__ updb,
    const float* __restrict__ updg, const float* __restrict__ updbe, int lvl)
{
    __shared__ float us[8][2*HH];
    __shared__ float sv[8][HH];
    __shared__ float smu[8], srs[8];
    int h  = threadIdx.x;
    int n0 = blockIdx.x << 3;
    int warp = h >> 5, lane = h & 31;

    #pragma unroll
    for (int nn = 0; nn < 8; nn++) {
        us[nn][h]      = g_x[(n0+nn)*HH + h];
        us[nn][HH + h] = g_msum[(n0+nn)*HH + h];
    }
    __syncthreads();

    const float* W = updW + (size_t)lvl*2*HH*HH;
    float bb = updb[lvl*HH + h];
    float acc[8];
    #pragma unroll
    for (int nn = 0; nn < 8; nn++) acc[nn] = bb;

    for (int k = 0; k < 2*HH; k++) {
        float w = W[k*HH + h];
        #pragma unroll
        for (int nn = 0; nn < 8; nn++)
            acc[nn] = fmaf(us[nn][k], w, acc[nn]);
    }

    float sl[8];
    #pragma unroll
    for (int nn = 0; nn < 8; nn++) {
        sl[nn] = silu_f(acc[nn]);
        sv[nn][h] = sl[nn];
    }
    __syncthreads();

    #pragma unroll
    for (int t = 0; t < 2; t++) {
        int nn = (warp << 1) + t;
        float v0 = sv[nn][lane], v1 = sv[nn][lane+32];
        float v2 = sv[nn][lane+64], v3 = sv[nn][lane+96];
        float p = (v0+v1) + (v2+v3);
        float q = fmaf(v0,v0, fmaf(v1,v1, fmaf(v2,v2, v3*v3)));
        #pragma unroll
        for (int off = 16; off; off >>= 1) {
            p += __shfl_xor_sync(0xffffffffu, p, off);
            q += __shfl_xor_sync(0xffffffffu, q, off);
        }
        if (lane == 0) {
            float mu = p * (1.f/HH);
            smu[nn] = mu;
            srs[nn] = rsqrtf(fmaf(-mu, mu, q * (1.f/HH)) + LN_EPS);
        }
    }
    __syncthreads();

    float gg = updg[lvl*HH + h], be = updbe[lvl*HH + h];
    float lm = 0.f;
    #pragma unroll
    for (int nn = 0; nn < 8; nn++) {
        float m  = fmaf((sl[nn] - smu[nn]) * srs[nn], gg, be);
        float xn = us[nn][h] + m;
        g_x[(n0+nn)*HH + h] = xn;
        lm += xn;
    }
    atomicAdd(&g_lmean[lvl*HH + h], lm * (1.f/NN));
}

// ---------------------------------------------------------------
__global__ void __launch_bounds__(256) k_final(
    const float* __restrict__ fpW, const float* __restrict__ fpb,
    const float* __restrict__ fpg, const float* __restrict__ fpbe,
    float* __restrict__ out)
{
    __shared__ float cs[NLVL*HH];
    __shared__ float rp[8], rq[8];
    __shared__ float s_mu, s_rstd;
    int t = threadIdx.x;
    int warp = t >> 5, lane = t & 31;

    for (int k = t; k < NLVL*HH; k += 256) cs[k] = g_lmean[k];
    __syncthreads();

    float acc = fpb[t];
    #pragma unroll 4
    for (int k = 0; k < NLVL*HH; k++) acc = fmaf(cs[k], fpW[k*DD + t], acc);

    float p = warp_sum(acc);
    float q = warp_sum(acc*acc);
    if (lane == 0) { rp[warp] = p; rq[warp] = q; }
    __syncthreads();
    if (t == 0) {
        float P = 0.f, Q = 0.f;
        #pragma unroll
        for (int w = 0; w < 8; w++) { P += rp[w]; Q += rq[w]; }
        float mu = P * (1.f/DD);
        s_mu = mu;
        s_rstd = rsqrtf(fmaf(-mu, mu, Q * (1.f/DD)) + LN_EPS);
    }
    __syncthreads();

    out[t] = fmaf((acc - s_mu) * s_rstd, fpg[t], fpbe[t]);
}

// ---------------------------------------------------------------
extern "C" void kernel_launch(void* const* d_in, const int* in_sizes, int n_in,
                              void* d_out, int out_size) {
    const int*   an    = (const int*)  d_in[0];
    const float* pos   = (const float*)d_in[1];
    const float* emb   = (const float*)d_in[2];
    const float* deW   = (const float*)d_in[3];
    const float* deb   = (const float*)d_in[4];
    const float* deg   = (const float*)d_in[5];
    const float* debe  = (const float*)d_in[6];
    const float* msgW  = (const float*)d_in[7];
    const float* msgb  = (const float*)d_in[8];
    const float* msgg  = (const float*)d_in[9];
    const float* msgbe = (const float*)d_in[10];
    const float* updW  = (const float*)d_in[11];
    const float* updb  = (const float*)d_in[12];
    const float* updg  = (const float*)d_in[13];
    const float* updbe = (const float*)d_in[14];
    const float* fpW   = (const float*)d_in[15];
    const float* fpb   = (const float*)d_in[16];
    const float* fpg   = (const float*)d_in[17];
    const float* fpbe  = (const float*)d_in[18];
    float* out = (float*)d_out;

    k_init<<<512, 256>>>(an, emb);
    k_tab<<<TGRID/8, 256>>>(deW, deb, deg, debe);
    for (int lvl = 0; lvl < NLVL; lvl++) {
        k_preprj<<<128, 128>>>(msgW, msgb, lvl);
        if (lvl == 0) k_msum<true><<<1024, 256>>>(pos, msgg, msgbe, lvl);
        else          k_msum<false><<<1024, 256>>>(pos, msgg, msgbe, lvl);
        k_upd<<<128, 128>>>(updW, updb, updg, updbe, lvl);
    }
    k_final<<<1, 256>>>(fpW, fpb, fpg, fpbe, out);
}